// round 17
// baseline (speedup 1.0000x reference)
#include <cuda_runtime.h>
#include <cstdint>

#define BATCH 32
#define T     1024
#define DIN   512
#define DH    512
#define M_TOT (BATCH * T)   // 32768

// scratch: X~ (64MB)
__device__ float g_X[(size_t)M_TOT * DH];

#define WLCAP 262144
__device__ int g_cnt;
__device__ int g_wl[WLCAP];

#define DELTA 1.2e-3f

// ---------------------------------------------------------------------------
__device__ __forceinline__ uint32_t smem_u32(const void* p) {
    uint32_t a;
    asm("{ .reg .u64 t; cvta.to.shared.u64 t, %1; cvt.u32.u64 %0, t; }"
        : "=r"(a) : "l"(p));
    return a;
}
#define CP_ASYNC16(sa, gp) \
    asm volatile("cp.async.cg.shared.global [%0], [%1], 16;" :: "r"(sa), "l"(gp))
#define CP_COMMIT() asm volatile("cp.async.commit_group;" ::: "memory")
#define CP_WAIT(n)  asm volatile("cp.async.wait_group %0;" :: "n"(n) : "memory")

__device__ __forceinline__ float cvt_tf32(float x) {
    uint32_t b;
    asm("cvt.rna.tf32.f32 %0, %1;" : "=r"(b) : "f"(x));
    return __uint_as_float(b);
}
__device__ __forceinline__ void mma_tf32(float c[4], const float a[4], const float b[2]) {
    asm volatile(
        "mma.sync.aligned.m16n8k8.row.col.f32.tf32.tf32.f32 "
        "{%0,%1,%2,%3}, {%4,%5,%6,%7}, {%8,%9}, {%0,%1,%2,%3};"
        : "+f"(c[0]), "+f"(c[1]), "+f"(c[2]), "+f"(c[3])
        : "r"(__float_as_uint(a[0])), "r"(__float_as_uint(a[1])),
          "r"(__float_as_uint(a[2])), "r"(__float_as_uint(a[3])),
          "r"(__float_as_uint(b[0])), "r"(__float_as_uint(b[1])));
}

// ---------------------------------------------------------------------------
// tf32 GEMM: 128x64 CTA tile, 8 warps (4x2) of 32x32, K-chunk 32, cp.async
// double buffer, cvt.rna fused on fragments. 3 CTAs/SM (launch_bounds).
// Per-element accumulation order identical to prior rounds -> bitwise-same X~.
// A is re-read by the 8 bn-tiles but stays L2-resident (64MB < 126MB L2).
// ---------------------------------------------------------------------------
#define BK      32
#define NCHUNK  (DIN / BK)          // 16
#define SROW    36
#define A_OFF   0
#define B_OFF   (128 * SROW)        // 4608 floats
#define BUF_FL  (B_OFF + 64 * SROW) // 6912 floats
#define SMEM_BYTES (2 * BUF_FL * 4) // 55296

__device__ __forceinline__ void issue_chunk(const float* __restrict__ A,
                                            const float* __restrict__ W,
                                            uint32_t sbuf, int bm, int bn,
                                            int k0, int tid)
{
#pragma unroll
    for (int q = 0; q < 4; q++) {           // A: 128 rows x 8 segs
        int u   = tid + q * 256;
        int row = u >> 3;
        int seg = u & 7;
        CP_ASYNC16(sbuf + A_OFF * 4 + row * (SROW * 4) + seg * 16,
                   A + (size_t)(bm + row) * DIN + k0 + seg * 4);
    }
#pragma unroll
    for (int q = 0; q < 2; q++) {           // B: 64 rows x 8 segs
        int u   = tid + q * 256;
        int row = u >> 3;
        int seg = u & 7;
        CP_ASYNC16(sbuf + B_OFF * 4 + row * (SROW * 4) + seg * 16,
                   W + (size_t)(bn + row) * DIN + k0 + seg * 4);
    }
}

__global__ __launch_bounds__(256, 3)
void gemm_tf32(const float* __restrict__ A, const float* __restrict__ W,
               const float* __restrict__ bias, float* __restrict__ X)
{
    extern __shared__ float sm[];
    const int tid  = threadIdx.x;
    const int lane = tid & 31;
    const int wid  = tid >> 5;
    const int g    = lane >> 2;
    const int tg   = lane & 3;
    const int wm   = wid >> 1;      // 0..3 -> 32-row band
    const int wn   = wid & 1;       // 0..1 -> 32-col band
    const int bm   = blockIdx.x * 128;
    const int bn   = blockIdx.y * 64;

    if (bm == 0 && bn == 0 && tid == 0) g_cnt = 0;   // fused zero_cnt

    const uint32_t sb0 = smem_u32(sm);

    float acc[2][4][4];
#pragma unroll
    for (int i = 0; i < 2; i++)
#pragma unroll
        for (int j = 0; j < 4; j++)
#pragma unroll
            for (int r = 0; r < 4; r++) acc[i][j][r] = 0.0f;

    issue_chunk(A, W, sb0, bm, bn, 0, tid);
    CP_COMMIT();

    for (int c = 0; c < NCHUNK; c++) {
        if (c + 1 < NCHUNK) {
            issue_chunk(A, W, sb0 + ((c + 1) & 1) * (BUF_FL * 4), bm, bn,
                        (c + 1) * BK, tid);
            CP_COMMIT();
            CP_WAIT(1);
        } else {
            CP_WAIT(0);
        }
        __syncthreads();

        const float* As = sm + (c & 1) * BUF_FL + A_OFF;
        const float* Bs = sm + (c & 1) * BUF_FL + B_OFF;

#pragma unroll
        for (int ks = 0; ks < 4; ks++) {
            const int kk = ks * 8;
            float a[2][4], b[4][2];
#pragma unroll
            for (int i = 0; i < 2; i++) {
                int row = wm * 32 + i * 16 + g;
                a[i][0] = cvt_tf32(As[(row     ) * SROW + kk + tg    ]);
                a[i][1] = cvt_tf32(As[(row +  8) * SROW + kk + tg    ]);
                a[i][2] = cvt_tf32(As[(row     ) * SROW + kk + tg + 4]);
                a[i][3] = cvt_tf32(As[(row +  8) * SROW + kk + tg + 4]);
            }
#pragma unroll
            for (int j = 0; j < 4; j++) {
                int n = wn * 32 + j * 8 + g;
                b[j][0] = cvt_tf32(Bs[n * SROW + kk + tg    ]);
                b[j][1] = cvt_tf32(Bs[n * SROW + kk + tg + 4]);
            }
#pragma unroll
            for (int i = 0; i < 2; i++)
#pragma unroll
                for (int j = 0; j < 4; j++)
                    mma_tf32(acc[i][j], a[i], b[j]);
        }
        __syncthreads();
    }

#pragma unroll
    for (int j = 0; j < 4; j++) {
        int col = bn + wn * 32 + j * 8 + tg * 2;
        float b0 = bias[col], b1 = bias[col + 1];
#pragma unroll
        for (int i = 0; i < 2; i++) {
            int row = bm + wm * 32 + i * 16 + g;
            float2 v0 = { acc[i][j][0] + b0, acc[i][j][1] + b1 };
            float2 v1 = { acc[i][j][2] + b0, acc[i][j][3] + b1 };
            *(float2*)(X + (size_t)row * DH + col)       = v0;
            *(float2*)(X + (size_t)(row + 8) * DH + col) = v1;
        }
    }
}

// ---------------------------------------------------------------------------
// Chunk-parallel scan on X~ with threshold + borderline flagging.
// ---------------------------------------------------------------------------
__global__ __launch_bounds__(256)
void scan2f(const float* __restrict__ X, const float* __restrict__ thr_p,
            float* __restrict__ out)
{
    const int bc    = blockIdx.x;
    const int b     = bc >> 4;
    const int chunk = (bc >> 1) & 7;
    const int half  = bc & 1;
    const int h     = half * 256 + threadIdx.x;

    const float AL  = 0.36787944117144233f;
    const float OMB = 1.0f - AL;
    const float thr = thr_p[0];

    const float* xp = X   + (size_t)b * T * DH + h;
    float*       op = out + (size_t)b * T * DH + h;

    const int t0 = chunk * 128;
    const int w0 = (t0 >= 96) ? (t0 - 96) : 0;
    const int base_lin = (b * T) * DH + h;

    float s = 0.0f, m = 0.0f;

    for (int t = w0; t < t0; t += 8) {
        float x[8];
#pragma unroll
        for (int u = 0; u < 8; u++) x[u] = xp[(size_t)(t + u) * DH];
#pragma unroll
        for (int u = 0; u < 8; u++) {
            s = fmaf(AL, s, x[u]);
            m = fmaf(AL, m, OMB * s);
        }
    }
    for (int t = t0; t < t0 + 128; t += 8) {
        float x[8], sp[8];
#pragma unroll
        for (int u = 0; u < 8; u++) x[u] = xp[(size_t)(t + u) * DH];
#pragma unroll
        for (int u = 0; u < 8; u++) {
            s = fmaf(AL, s, x[u]);
            m = fmaf(AL, m, OMB * s);
            float d = m - thr;
            sp[u] = (d > 0.0f) ? 1.0f : 0.0f;
            if (fabsf(d) < DELTA) {
                int idx = atomicAdd(&g_cnt, 1);
                if (idx < WLCAP) g_wl[idx] = base_lin + (t + u) * DH;
            }
        }
#pragma unroll
        for (int u = 0; u < 8; u++) op[(size_t)(t + u) * DH] = sp[u];
    }
}

// ---------------------------------------------------------------------------
// Patch: recompute flagged elements with the R1-exact float-op sequence.
// 20-step warmup (window <= 21 rows; discarded-tail weight ~1.7e-8 ->
// flip probability ~6e-5 across all items). cp.async double-buffered
// k-tiles; LDS-broadcast final scan.
// ---------------------------------------------------------------------------
#define PROWS 21
#define PSTR  68     // floats per smem row (64 + 4; 272B, 16B aligned)

__global__ __launch_bounds__(32)
void patch(const float* __restrict__ X, const float* __restrict__ W,
           const float* __restrict__ bias, const float* __restrict__ thr_p,
           float* __restrict__ OUT)
{
    __shared__ __align__(16) float As[2][PROWS * PSTR];  // 2 x 5712 B
    __shared__ __align__(16) float Ws[DIN];              // 2048 B
    __shared__ float sx[32];

    const int lane = threadIdx.x;
    const int cnt  = min(g_cnt, WLCAP);

    const float AL  = 0.36787944117144233f;
    const float OMB = 1.0f - AL;
    const float thr = thr_p[0];

    const uint32_t as_base = smem_u32(&As[0][0]);

    for (int it = blockIdx.x; it < cnt; it += gridDim.x) {
        int lin = g_wl[it];
        int h  = lin & (DH - 1);
        int bt = lin >> 9;
        int t  = bt & (T - 1);
        int b  = bt >> 10;

        int tw = (t >= 20) ? (t - 20) : 0;
        int nT = t - tw + 1;   // <= 21

        // stage W row (coalesced)
#pragma unroll
        for (int q = 0; q < 4; q++) {
            int k = q * 128 + lane * 4;
            *(float4*)&Ws[k] = *(const float4*)(W + (size_t)h * DIN + k);
        }
        float bh = bias[h];

        // lane owns dot for window row lane (clamped)
        int r_ln = ((tw + lane <= t) ? (tw + lane) : t) - tw;

        const float* xbase = X + ((size_t)b * T + tw) * DIN;
        const int nld = nT * 16;   // float4 loads per tile

        for (int u = lane; u < nld; u += 32) {
            int r = u >> 4, cc = u & 15;
            CP_ASYNC16(as_base + (r * PSTR + cc * 4) * 4,
                       xbase + (size_t)r * DIN + cc * 4);
        }
        CP_COMMIT();

        float acc = 0.0f;

        for (int kt = 0; kt < 8; kt++) {
            if (kt + 1 < 8) {
                uint32_t dstb = as_base + ((kt + 1) & 1) * (PROWS * PSTR * 4);
                const float* src = xbase + (kt + 1) * 64;
                for (int u = lane; u < nld; u += 32) {
                    int r = u >> 4, cc = u & 15;
                    CP_ASYNC16(dstb + (r * PSTR + cc * 4) * 4,
                               src + (size_t)r * DIN + cc * 4);
                }
                CP_COMMIT();
                CP_WAIT(1);
            } else {
                CP_WAIT(0);
            }
            __syncwarp();

            const float* ar = &As[kt & 1][r_ln * PSTR];
            const float* wr = &Ws[kt * 64];
            float a = acc;
#pragma unroll
            for (int cq = 0; cq < 16; cq++) {
                float4 a4 = *(const float4*)&ar[cq * 4];
                float4 w4 = *(const float4*)&wr[cq * 4];
                a = fmaf(a4.x, w4.x, a);
                a = fmaf(a4.y, w4.y, a);
                a = fmaf(a4.z, w4.z, a);
                a = fmaf(a4.w, w4.w, a);
            }
            acc = a;
            __syncwarp();
        }

        sx[lane] = acc + bh;
        __syncwarp();

        float s = 0.0f, m = 0.0f;
        for (int q = 0; q < nT; q++) {
            float x = sx[q];
            s = fmaf(AL, s, x);
            m = fmaf(AL, m, OMB * s);
        }
        if (lane == 0)
            OUT[lin] = (m > thr) ? 1.0f : 0.0f;
        __syncwarp();
    }
}

// ---------------------------------------------------------------------------
extern "C" void kernel_launch(void* const* d_in, const int* in_sizes, int n_in,
                              void* d_out, int out_size)
{
    const float* inputs = (const float*)d_in[0];
    const float* W      = (const float*)d_in[1];
    const float* bias   = (const float*)d_in[2];
    const float* thr    = (const float*)d_in[3];
    float*       out    = (float*)d_out;

    float* Xs;
    cudaGetSymbolAddress((void**)&Xs, g_X);

    cudaFuncSetAttribute(gemm_tf32, cudaFuncAttributeMaxDynamicSharedMemorySize, SMEM_BYTES);

    dim3 ggrid(M_TOT / 128, DH / 64);   // (256, 8)
    gemm_tf32<<<ggrid, 256, SMEM_BYTES>>>(inputs, W, bias, Xs);

    scan2f<<<512, 256>>>(Xs, thr, out);
    patch<<<4096, 32>>>(inputs, W, bias, thr, out);
}